// round 12
// baseline (speedup 1.0000x reference)
#include <cuda_runtime.h>
#include <cuda_bf16.h>

// MedianFilter1D: x[16, 64, 16384] fp32, window k=9, zero padding.
// 1024 rows x 16384 = 2,097,152 chunks of 8 outputs.
//
// Round 12 — triple-buffered grid-strided pipeline. In-flight-bytes model:
// DRAM needs ~2.4 MB outstanding chip-wide (8TB/s x ~300ns); double buffering
// gives only ~1.8 MB -> DRAM stuck ~50% in every previous round. Keep TWO
// LDG.256 in flight per warp during compute:
//   ld c0, ld c1, ld c2 | proc c0, ld c3 | proc c1 | proc c2 | proc c3
// launch_bounds(256,5) -> ~51 regs allowed, 3rd buffer fits without spills.
//
// Compute: sort 7 adjacent pairs; sorted-4 runs via 3-CE merge of sorted
// pairs; ranks 3,4 of each window-pair's shared 8 via pruned odd-even
// merge(4,4); median9 = clamp(inserted, s3, s4).

#define CE(a, b) { float _lo = fminf(a, b); float _hi = fmaxf(a, b); (a) = _lo; (b) = _hi; }

__device__ __forceinline__ void ld_in8(const float* p, float* v)
{
    asm volatile(
        "ld.global.nc.L2::evict_last.v8.f32 {%0,%1,%2,%3,%4,%5,%6,%7}, [%8];"
        : "=f"(v[0]), "=f"(v[1]), "=f"(v[2]), "=f"(v[3]),
          "=f"(v[4]), "=f"(v[5]), "=f"(v[6]), "=f"(v[7])
        : "l"(p));
}

__device__ __forceinline__ void st_out8(float* p, const float* o)
{
    asm volatile(
        "st.global.L2::evict_first.v8.f32 [%0], {%1,%2,%3,%4,%5,%6,%7,%8};"
        :: "l"(p),
           "f"(o[0]), "f"(o[1]), "f"(o[2]), "f"(o[3]),
           "f"(o[4]), "f"(o[5]), "f"(o[6]), "f"(o[7])
        : "memory");
}

static constexpr int L       = 16384;
static constexpr int ROWS    = 16 * 64;
static constexpr int TPB     = 256;
static constexpr int NCHUNK  = ROWS * (L / 8);        // 2,097,152
static constexpr int GRID    = 2048;
static constexpr int STRIDE  = GRID * TPB;            // 524,288 threads
static constexpr int ITERS   = NCHUNK / STRIDE;       // 4

__device__ __forceinline__ void process_chunk(
    const float* __restrict__ x, float* __restrict__ y,
    const float* own, int c, int lane)
{
    const unsigned FULL = 0xFFFFFFFFu;
    float v[16];
    #pragma unroll
    for (int i = 0; i < 8; i++) v[4 + i] = own[i];

    // Halos from neighbor lanes (consecutive c across lanes).
    float4 lh, rh;
    lh.x = __shfl_up_sync(FULL, v[8],  1);
    lh.y = __shfl_up_sync(FULL, v[9],  1);
    lh.z = __shfl_up_sync(FULL, v[10], 1);
    lh.w = __shfl_up_sync(FULL, v[11], 1);
    rh.x = __shfl_down_sync(FULL, v[4], 1);
    rh.y = __shfl_down_sync(FULL, v[5], 1);
    rh.z = __shfl_down_sync(FULL, v[6], 1);
    rh.w = __shfl_down_sync(FULL, v[7], 1);

    int cm = c & 2047;   // chunk position within its row
    if (lane == 0) {
        if (cm != 0) lh = __ldg(reinterpret_cast<const float4*>(x + 8 * (size_t)c - 4));
        else         lh = make_float4(0.f, 0.f, 0.f, 0.f);
    }
    if (lane == 31) {
        if (cm != 2047) rh = __ldg(reinterpret_cast<const float4*>(x + 8 * (size_t)c + 8));
        else            rh = make_float4(0.f, 0.f, 0.f, 0.f);
    }
    v[0]  = lh.x; v[1]  = lh.y; v[2]  = lh.z; v[3]  = lh.w;
    v[12] = rh.x; v[13] = rh.y; v[14] = rh.z; v[15] = rh.w;

    // Sorted pairs P_j = sorted(v[2j+1], v[2j+2]), j = 0..6.
    float pl[7], ph[7];
    #pragma unroll
    for (int j = 0; j < 7; j++) {
        pl[j] = fminf(v[2*j + 1], v[2*j + 2]);
        ph[j] = fmaxf(v[2*j + 1], v[2*j + 2]);
    }

    // Runs R[i] = sorted-4 of v[2i+1 .. 2i+5) = merge(P_i, P_{i+1}), 3 CE.
    float R[6][4];
    #pragma unroll
    for (int i = 0; i < 6; i++) {
        float x0 = pl[i], x1 = ph[i], x2 = pl[i + 1], x3 = ph[i + 1];
        CE(x0, x2) CE(x1, x3) CE(x1, x2)
        R[i][0] = x0; R[i][1] = x1; R[i][2] = x2; R[i][3] = x3;
    }

    float o[8];
    #pragma unroll
    for (int j = 0; j < 4; j++) {
        int b = 2 * j;
        const float* A = R[j];       // sorted v[b+1 .. b+5)
        const float* B = R[j + 2];   // sorted v[b+5 .. b+9)
        float e2 = fmaxf(fmaxf(A[0], B[0]), fminf(A[2], B[2]));
        float o1 = fminf(fmaxf(A[1], B[1]), fminf(A[3], B[3]));
        float s3 = fminf(o1, e2);
        float s4 = fmaxf(o1, e2);
        o[b]     = fminf(fmaxf(v[b],     s3), s4);
        o[b + 1] = fminf(fmaxf(v[b + 9], s3), s4);
    }

    st_out8(y + 8 * (size_t)c, o);
}

__global__ __launch_bounds__(TPB, 5)
void median9_kernel(const float* __restrict__ x, float* __restrict__ y)
{
    int t    = blockIdx.x * TPB + threadIdx.x;
    int lane = threadIdx.x & 31;

    static_assert(ITERS == 4, "pipeline is hand-unrolled for 4 iterations");

    int c0 = t;
    int c1 = t + STRIDE;
    int c2 = t + 2 * STRIDE;
    int c3 = t + 3 * STRIDE;

    float A[8], B[8], C[8];
    ld_in8(x + 8 * (size_t)c0, A);    // in flight: A
    ld_in8(x + 8 * (size_t)c1, B);    // in flight: A, B
    ld_in8(x + 8 * (size_t)c2, C);    // in flight: A, B, C

    process_chunk(x, y, A, c0, lane); // consumes A; B, C still in flight
    ld_in8(x + 8 * (size_t)c3, A);    // refill A; in flight: B(done?), C, A

    process_chunk(x, y, B, c1, lane); // C, A in flight
    process_chunk(x, y, C, c2, lane); // A in flight
    process_chunk(x, y, A, c3, lane);
}

extern "C" void kernel_launch(void* const* d_in, const int* in_sizes, int n_in,
                              void* d_out, int out_size)
{
    const float* x = (const float*)d_in[0];
    float* y = (float*)d_out;
    median9_kernel<<<GRID, TPB>>>(x, y);
}

// round 13
// speedup vs baseline: 1.1146x; 1.1146x over previous
#include <cuda_runtime.h>
#include <cuda_bf16.h>

// MedianFilter1D: x[16, 64, 16384] fp32, window k=9, zero padding.
// 1024 rows x 16384 = 2,097,152 chunks of 8 outputs.
//
// Round 13 — single-wave persistent kernel + rolling double-buffer pipeline.
// R12 killed the MLP-depth theory (deeper buffering regressed). Remaining
// structural waste in R8: 2048 blocks = 2.3 waves (transition bubbles, ragged
// tail) and a 4-deep pipeline whose prologue/epilogue leaves 25% of the span
// with no load in flight. Fix: GRID = 148 SMs x 6 blocks = 888, all blocks
// resident (launch_bounds(256,6) caps regs at 42); each thread walks 9-10
// grid-strided chunks with "load next, then compute current" rolling overlap.
//
// Compute (best known, ~9 FMNMX/output): sort 7 adjacent pairs; sorted-4 runs
// via 3-CE merge of sorted pairs; ranks 3,4 of each window-pair's shared 8
// via pruned odd-even merge(4,4); median9 = clamp(inserted, s3, s4).

#define CE(a, b) { float _lo = fminf(a, b); float _hi = fmaxf(a, b); (a) = _lo; (b) = _hi; }

__device__ __forceinline__ void ld_in8(const float* p, float* v)
{
    asm volatile(
        "ld.global.nc.L2::evict_last.v8.f32 {%0,%1,%2,%3,%4,%5,%6,%7}, [%8];"
        : "=f"(v[0]), "=f"(v[1]), "=f"(v[2]), "=f"(v[3]),
          "=f"(v[4]), "=f"(v[5]), "=f"(v[6]), "=f"(v[7])
        : "l"(p));
}

__device__ __forceinline__ void st_out8(float* p, const float* o)
{
    asm volatile(
        "st.global.L2::evict_first.v8.f32 [%0], {%1,%2,%3,%4,%5,%6,%7,%8};"
        :: "l"(p),
           "f"(o[0]), "f"(o[1]), "f"(o[2]), "f"(o[3]),
           "f"(o[4]), "f"(o[5]), "f"(o[6]), "f"(o[7])
        : "memory");
}

static constexpr int L      = 16384;
static constexpr int ROWS   = 16 * 64;
static constexpr int TPB    = 256;
static constexpr int NCHUNK = ROWS * (L / 8);     // 2,097,152
static constexpr int GRID   = 148 * 6;            // 888 blocks, single wave
static constexpr int STRIDE = GRID * TPB;         // 227,328 threads

__device__ __forceinline__ void process_chunk(
    const float* __restrict__ x, float* __restrict__ y,
    const float* own, int c, int lane)
{
    const unsigned FULL = 0xFFFFFFFFu;
    float v[16];
    #pragma unroll
    for (int i = 0; i < 8; i++) v[4 + i] = own[i];

    // Halos from neighbor lanes (consecutive c across lanes).
    float4 lh, rh;
    lh.x = __shfl_up_sync(FULL, v[8],  1);
    lh.y = __shfl_up_sync(FULL, v[9],  1);
    lh.z = __shfl_up_sync(FULL, v[10], 1);
    lh.w = __shfl_up_sync(FULL, v[11], 1);
    rh.x = __shfl_down_sync(FULL, v[4], 1);
    rh.y = __shfl_down_sync(FULL, v[5], 1);
    rh.z = __shfl_down_sync(FULL, v[6], 1);
    rh.w = __shfl_down_sync(FULL, v[7], 1);

    int cm = c & 2047;   // chunk position within its row
    if (lane == 0) {
        if (cm != 0) lh = __ldg(reinterpret_cast<const float4*>(x + 8 * (size_t)c - 4));
        else         lh = make_float4(0.f, 0.f, 0.f, 0.f);
    }
    if (lane == 31) {
        if (cm != 2047) rh = __ldg(reinterpret_cast<const float4*>(x + 8 * (size_t)c + 8));
        else            rh = make_float4(0.f, 0.f, 0.f, 0.f);
    }
    v[0]  = lh.x; v[1]  = lh.y; v[2]  = lh.z; v[3]  = lh.w;
    v[12] = rh.x; v[13] = rh.y; v[14] = rh.z; v[15] = rh.w;

    // Sorted pairs P_j = sorted(v[2j+1], v[2j+2]), j = 0..6.
    float pl[7], ph[7];
    #pragma unroll
    for (int j = 0; j < 7; j++) {
        pl[j] = fminf(v[2*j + 1], v[2*j + 2]);
        ph[j] = fmaxf(v[2*j + 1], v[2*j + 2]);
    }

    // Runs R[i] = sorted-4 of v[2i+1 .. 2i+5) = merge(P_i, P_{i+1}), 3 CE.
    float R[6][4];
    #pragma unroll
    for (int i = 0; i < 6; i++) {
        float x0 = pl[i], x1 = ph[i], x2 = pl[i + 1], x3 = ph[i + 1];
        CE(x0, x2) CE(x1, x3) CE(x1, x2)
        R[i][0] = x0; R[i][1] = x1; R[i][2] = x2; R[i][3] = x3;
    }

    float o[8];
    #pragma unroll
    for (int j = 0; j < 4; j++) {
        int b = 2 * j;
        const float* A = R[j];       // sorted v[b+1 .. b+5)
        const float* B = R[j + 2];   // sorted v[b+5 .. b+9)
        float e2 = fmaxf(fmaxf(A[0], B[0]), fminf(A[2], B[2]));
        float o1 = fminf(fmaxf(A[1], B[1]), fminf(A[3], B[3]));
        float s3 = fminf(o1, e2);
        float s4 = fmaxf(o1, e2);
        o[b]     = fminf(fmaxf(v[b],     s3), s4);
        o[b + 1] = fminf(fmaxf(v[b + 9], s3), s4);
    }

    st_out8(y + 8 * (size_t)c, o);
}

__global__ __launch_bounds__(TPB, 6)
void median9_kernel(const float* __restrict__ x, float* __restrict__ y)
{
    int t    = blockIdx.x * TPB + threadIdx.x;
    int lane = threadIdx.x & 31;

    float A[8], B[8];
    int c = t;
    ld_in8(x + 8 * (size_t)c, A);          // prologue load

    // Rolling pipeline: load c+STRIDE while computing c. 9-10 iters/thread.
    #pragma unroll 1
    for (;;) {
        int cn = c + STRIDE;
        bool more = cn < NCHUNK;
        if (more) ld_in8(x + 8 * (size_t)cn, B);
        process_chunk(x, y, A, c, lane);
        if (!more) break;
        c = cn;
        #pragma unroll
        for (int i = 0; i < 8; i++) A[i] = B[i];
    }
}

extern "C" void kernel_launch(void* const* d_in, const int* in_sizes, int n_in,
                              void* d_out, int out_size)
{
    const float* x = (const float*)d_in[0];
    float* y = (float*)d_out;
    median9_kernel<<<GRID, TPB>>>(x, y);
}